// round 3
// baseline (speedup 1.0000x reference)
#include <cuda_runtime.h>
#include <cstdint>

#define B_SZ 512
#define A_SZ 1024
#define EDIM 256
#define RDIM 256
#define HDIM 512
#define ADIM 512   // action_dim = EDIM + RDIM
#define XDIM 1024  // ADIM + HDIM
#define NREL 500

// scratch (no allocations allowed)
__device__ float g_Xcat[B_SZ * XDIM];
__device__ float g_X1[B_SZ * ADIM];
__device__ float g_X2[B_SZ * ADIM];
__device__ float g_relS[B_SZ * 512];   // [B, 500] padded to 512

// ---------------------------------------------------------------------------
// concat [e_t | H | r_q] -> Xcat [512, 1024]
// ---------------------------------------------------------------------------
__global__ void concat_kernel(const float* __restrict__ e_t,
                              const float* __restrict__ Hs,
                              const float* __restrict__ r_q) {
    int i = blockIdx.x * blockDim.x + threadIdx.x;
    if (i >= B_SZ * XDIM) return;
    int b = i >> 10;
    int k = i & 1023;
    float v;
    if (k < 256)       v = e_t[b * 256 + k];
    else if (k < 768)  v = Hs[b * 512 + (k - 256)];
    else               v = r_q[b * 256 + (k - 768)];
    g_Xcat[i] = v;
}

// ---------------------------------------------------------------------------
// C[M,N] = A[M,K] * B[N,K]^T  (+bias, +relu)   A row-major lda, B row-major ldb
// BM=32, BN=64, BK=16, 128 threads, 4x4 per thread
// ---------------------------------------------------------------------------
template<bool RELU, bool BIAS>
__global__ void __launch_bounds__(128) gemm_abt(
    const float* __restrict__ A, int lda,
    const float* __restrict__ Bm, int ldb,
    const float* __restrict__ bias,
    float* __restrict__ C, int ldc,
    int M, int N, int K) {
    const int BM = 32, BN = 64, BK = 16;
    __shared__ float As[BK][BM];
    __shared__ float Bs[BK][BN];

    int tid = threadIdx.x;
    int tx = tid & 15;        // 0..15 -> n
    int ty = tid >> 4;        // 0..7  -> m
    int m0 = blockIdx.y * BM;
    int n0 = blockIdx.x * BN;

    int lr = tid >> 2;        // 0..31
    int lc = (tid & 3) * 4;   // 0,4,8,12

    float acc[4][4] = {};

    for (int k0 = 0; k0 < K; k0 += BK) {
        // A tile: 32 rows x 16 cols; one float4 per thread
        {
            float4 v = *(const float4*)(A + (size_t)(m0 + lr) * lda + k0 + lc);
            As[lc + 0][lr] = v.x; As[lc + 1][lr] = v.y;
            As[lc + 2][lr] = v.z; As[lc + 3][lr] = v.w;
        }
        // B tile: 64 rows x 16 cols; two float4 per thread
        {
            int n1 = n0 + lr;
            float4 v = (n1 < N) ? *(const float4*)(Bm + (size_t)n1 * ldb + k0 + lc)
                                : make_float4(0.f, 0.f, 0.f, 0.f);
            Bs[lc + 0][lr] = v.x; Bs[lc + 1][lr] = v.y;
            Bs[lc + 2][lr] = v.z; Bs[lc + 3][lr] = v.w;
            int n2 = n0 + lr + 32;
            float4 w = (n2 < N) ? *(const float4*)(Bm + (size_t)n2 * ldb + k0 + lc)
                                : make_float4(0.f, 0.f, 0.f, 0.f);
            Bs[lc + 0][lr + 32] = w.x; Bs[lc + 1][lr + 32] = w.y;
            Bs[lc + 2][lr + 32] = w.z; Bs[lc + 3][lr + 32] = w.w;
        }
        __syncthreads();

        #pragma unroll
        for (int kk = 0; kk < BK; kk++) {
            float a[4], bb[4];
            *(float4*)a  = *(const float4*)&As[kk][ty * 4];
            *(float4*)bb = *(const float4*)&Bs[kk][tx * 4];
            #pragma unroll
            for (int i = 0; i < 4; i++)
                #pragma unroll
                for (int j = 0; j < 4; j++)
                    acc[i][j] = fmaf(a[i], bb[j], acc[i][j]);
        }
        __syncthreads();
    }

    #pragma unroll
    for (int i = 0; i < 4; i++) {
        int m = m0 + ty * 4 + i;
        if (m >= M) continue;
        #pragma unroll
        for (int j = 0; j < 4; j++) {
            int n = n0 + tx * 4 + j;
            if (n >= N) continue;
            float v = acc[i][j];
            if (BIAS) v += bias[n];
            if (RELU) v = fmaxf(v, 0.f);
            C[(size_t)m * ldc + n] = v;
        }
    }
}

// ---------------------------------------------------------------------------
// Threefry-2x32 (20 rounds), returns BOTH output words.
// ---------------------------------------------------------------------------
__device__ __forceinline__ void threefry2x32(uint32_t k0, uint32_t k1,
                                             uint32_t x0, uint32_t x1,
                                             uint32_t& o0, uint32_t& o1) {
    uint32_t k2 = k0 ^ k1 ^ 0x1BD11BDAu;
    x0 += k0; x1 += k1;
#define TF_R(r) { x0 += x1; x1 = (x1 << (r)) | (x1 >> (32 - (r))); x1 ^= x0; }
    TF_R(13) TF_R(15) TF_R(26) TF_R(6)   x0 += k1; x1 += k2 + 1u;
    TF_R(17) TF_R(29) TF_R(16) TF_R(24)  x0 += k2; x1 += k0 + 2u;
    TF_R(13) TF_R(15) TF_R(26) TF_R(6)   x0 += k0; x1 += k1 + 3u;
    TF_R(17) TF_R(29) TF_R(16) TF_R(24)  x0 += k1; x1 += k2 + 4u;
    TF_R(13) TF_R(15) TF_R(26) TF_R(6)   x0 += k2; x1 += k0 + 5u;
#undef TF_R
    o0 = x0; o1 = x1;
}

// JAX PARTITIONABLE threefry random bits, bit_width=32:
//   counts = iota(uint64, N); per element i: (hi, lo) = (i>>32, i&0xffffffff)
//   bits1, bits2 = threefry2x32(key, (hi, lo));  bits = bits1 ^ bits2
// Here N = 524288 < 2^32 so hi = 0.
__device__ __forceinline__ uint32_t jax_bits_partitionable_xor(uint32_t i) {
    uint32_t o0, o1;
    threefry2x32(0u, 42u, 0u, i, o0, o1);
    return o0 ^ o1;
}

// ---------------------------------------------------------------------------
// Per-row: ent scores + rel lookup, masked softmax, entropy, gumbel argmax.
// 1 block per batch row, 256 threads (8 warps).
// ---------------------------------------------------------------------------
__global__ void __launch_bounds__(256) score_softmax_sample(
    const int* __restrict__ r_space,
    const int* __restrict__ e_space,
    const float* __restrict__ mask,
    const float* __restrict__ ent_emb,
    float* __restrict__ out) {
    int b = blockIdx.x;
    int tid = threadIdx.x;
    int lane = tid & 31;
    int w = tid >> 5;

    __shared__ float sX2[256];
    __shared__ float sSc[1024];
    __shared__ float sMax[8];
    __shared__ float sSum[8];
    __shared__ float sV[8];
    __shared__ float sE[8];
    __shared__ int   sI[8];

    if (tid < 256) sX2[tid] = g_X2[(size_t)b * 512 + 256 + tid];
    __syncthreads();

    float x[8];
    #pragma unroll
    for (int j = 0; j < 8; j++) x[j] = sX2[lane * 8 + j];

    const int base = b * A_SZ;

    // ---- scores ----
    for (int it = 0; it < 128; it++) {
        int a = w * 128 + it;
        int e = e_space[base + a];
        const float4* ep = (const float4*)(ent_emb + (size_t)e * 256 + lane * 8);
        float4 v0 = ep[0];
        float4 v1 = ep[1];
        float s = v0.x * x[0] + v0.y * x[1] + v0.z * x[2] + v0.w * x[3]
                + v1.x * x[4] + v1.y * x[5] + v1.z * x[6] + v1.w * x[7];
        #pragma unroll
        for (int o = 16; o; o >>= 1) s += __shfl_xor_sync(0xFFFFFFFFu, s, o);
        if (lane == 0) {
            int r = r_space[base + a];
            float sc = s + g_relS[(size_t)b * 512 + r];
            float m = mask[base + a];
            sSc[a] = sc - (1.0f - m) * 1e9f;
        }
    }
    __syncthreads();

    // ---- max ----
    float mx = -__int_as_float(0x7F800000);  // -inf
    for (int j = tid; j < 1024; j += 256) mx = fmaxf(mx, sSc[j]);
    #pragma unroll
    for (int o = 16; o; o >>= 1) mx = fmaxf(mx, __shfl_xor_sync(0xFFFFFFFFu, mx, o));
    if (lane == 0) sMax[w] = mx;
    __syncthreads();
    mx = sMax[0];
    #pragma unroll
    for (int i = 1; i < 8; i++) mx = fmaxf(mx, sMax[i]);

    // ---- exp & sum ----
    float sum = 0.f;
    for (int j = tid; j < 1024; j += 256) {
        float e = expf(sSc[j] - mx);
        sSc[j] = e;
        sum += e;
    }
    #pragma unroll
    for (int o = 16; o; o >>= 1) sum += __shfl_xor_sync(0xFFFFFFFFu, sum, o);
    if (lane == 0) sSum[w] = sum;
    __syncthreads();
    float total = 0.f;
    #pragma unroll
    for (int i = 0; i < 8; i++) total += sSum[i];

    // ---- p, entropy, gumbel argmax ----
    float ent = 0.f;
    float bestV = -__int_as_float(0x7F800000);
    int bestI = 0x7FFFFFFF;
    for (int j = tid; j < 1024; j += 256) {
        float p = sSc[j] / total;
        sSc[j] = p;
        out[1536 + base + j] = p;                 // action_dist
        float lp = logf(p + 1e-30f);
        ent += p * lp;
        uint32_t bits = jax_bits_partitionable_xor((uint32_t)(base + j));
        float f = __uint_as_float((bits >> 9) | 0x3F800000u) - 1.0f;
        float u = fmaxf(f, 1.17549435e-38f);
        float g = -logf(-logf(u));
        float v = lp + g;
        if (v > bestV || (v == bestV && j < bestI)) { bestV = v; bestI = j; }
    }
    #pragma unroll
    for (int o = 16; o; o >>= 1) {
        float ov = __shfl_xor_sync(0xFFFFFFFFu, bestV, o);
        int   oi = __shfl_xor_sync(0xFFFFFFFFu, bestI, o);
        float oe = __shfl_xor_sync(0xFFFFFFFFu, ent, o);
        ent += oe;
        if (ov > bestV || (ov == bestV && oi < bestI)) { bestV = ov; bestI = oi; }
    }
    if (lane == 0) { sV[w] = bestV; sI[w] = bestI; sE[w] = ent; }
    __syncthreads();

    if (tid == 0) {
        float bv = sV[0]; int bi = sI[0]; float te = sE[0];
        #pragma unroll
        for (int i = 1; i < 8; i++) {
            te += sE[i];
            if (sV[i] > bv || (sV[i] == bv && sI[i] < bi)) { bv = sV[i]; bi = sI[i]; }
        }
        out[b]        = sSc[bi];                          // action_prob
        out[512 + b]  = (float)r_space[base + bi];        // next_r
        out[1024 + b] = (float)e_space[base + bi];        // next_e
        out[525824 + b] = -te;                            // entropy
    }
}

// ---------------------------------------------------------------------------
extern "C" void kernel_launch(void* const* d_in, const int* in_sizes, int n_in,
                              void* d_out, int out_size) {
    const float* e_t     = (const float*)d_in[0];
    const float* Hs      = (const float*)d_in[1];
    const float* r_q     = (const float*)d_in[2];
    const int*   r_space = (const int*)d_in[3];
    const int*   e_space = (const int*)d_in[4];
    const float* mask    = (const float*)d_in[5];
    const float* W1_w    = (const float*)d_in[6];
    const float* W1_b    = (const float*)d_in[7];
    const float* W2_w    = (const float*)d_in[8];
    const float* W2_b    = (const float*)d_in[9];
    const float* rel_emb = (const float*)d_in[10];
    const float* ent_emb = (const float*)d_in[11];
    float* out = (float*)d_out;

    float *Xcat, *X1, *X2, *relS;
    cudaGetSymbolAddress((void**)&Xcat, g_Xcat);
    cudaGetSymbolAddress((void**)&X1,   g_X1);
    cudaGetSymbolAddress((void**)&X2,   g_X2);
    cudaGetSymbolAddress((void**)&relS, g_relS);

    concat_kernel<<<(B_SZ * XDIM + 255) / 256, 256>>>(e_t, Hs, r_q);

    dim3 g1(512 / 64, 512 / 32);
    // X1 = relu(Xcat @ W1^T + b1)
    gemm_abt<true, true><<<g1, 128>>>(Xcat, XDIM, W1_w, XDIM, W1_b, X1, ADIM,
                                      B_SZ, ADIM, XDIM);
    // X2 = X1 @ W2^T + b2
    gemm_abt<false, true><<<g1, 128>>>(X1, ADIM, W2_w, ADIM, W2_b, X2, ADIM,
                                       B_SZ, ADIM, ADIM);
    // relS[b, j] = X2[b, :256] . rel_emb[j]
    dim3 g3((NREL + 63) / 64, 512 / 32);
    gemm_abt<false, false><<<g3, 128>>>(X2, ADIM, rel_emb, RDIM, nullptr, relS, 512,
                                        B_SZ, NREL, RDIM);

    score_softmax_sample<<<B_SZ, 256>>>(r_space, e_space, mask, ent_emb, out);
}

// round 4
// speedup vs baseline: 1.1925x; 1.1925x over previous
#include <cuda_runtime.h>
#include <cstdint>

#define B_SZ 512
#define A_SZ 1024
#define ADIM 512
#define XDIM 1024
#define NREL 500
#define MN (512 * 512)

// scratch (device globals; no allocation allowed)
__device__ float g_X1p[8 * MN];   // gemm1 split-K partials
__device__ float g_X1[MN];        // relu(X1 + b1)
__device__ float g_X2p[4 * MN];   // gemm2 split-K partials (bias NOT added)
__device__ float g_relSp[2 * MN]; // relS split-K partials

__device__ __forceinline__ float4 ld4(const float* p) { return *(const float4*)p; }

// ---------------------------------------------------------------------------
// GEMM1 fused concat: X1p[sk] += [e_t|H|r_q] @ W1^T  (chunk 128 of K=1024)
// 64x64 tile, 256 threads, 4x4 per thread. grid (8,8,8).
// ---------------------------------------------------------------------------
__global__ void __launch_bounds__(256) gemm1_fused(
    const float* __restrict__ e_t, const float* __restrict__ Hs,
    const float* __restrict__ r_q, const float* __restrict__ W1) {
    __shared__ float As[16][64];
    __shared__ float Bs[16][64];
    const int t = threadIdx.x;
    const int m0 = blockIdx.y * 64, n0 = blockIdx.x * 64;
    const int lr = t >> 2, lc = (t & 3) * 4;
    const int tx = t & 15, ty = t >> 4;
    float acc[4][4] = {};
    const int kbeg = blockIdx.z * 128;

    for (int k0 = kbeg; k0 < kbeg + 128; k0 += 16) {
        int k = k0 + lc;
        int m = m0 + lr;
        float4 va;
        if (k < 256)      va = ld4(e_t + m * 256 + k);
        else if (k < 768) va = ld4(Hs + m * 512 + (k - 256));
        else              va = ld4(r_q + m * 256 + (k - 768));
        As[lc + 0][lr] = va.x; As[lc + 1][lr] = va.y;
        As[lc + 2][lr] = va.z; As[lc + 3][lr] = va.w;
        float4 vb = ld4(W1 + (size_t)(n0 + lr) * XDIM + k);
        Bs[lc + 0][lr] = vb.x; Bs[lc + 1][lr] = vb.y;
        Bs[lc + 2][lr] = vb.z; Bs[lc + 3][lr] = vb.w;
        __syncthreads();
        #pragma unroll
        for (int kk = 0; kk < 16; kk++) {
            float a[4], bb[4];
            *(float4*)a  = *(const float4*)&As[kk][ty * 4];
            *(float4*)bb = *(const float4*)&Bs[kk][tx * 4];
            #pragma unroll
            for (int i = 0; i < 4; i++)
                #pragma unroll
                for (int j = 0; j < 4; j++)
                    acc[i][j] = fmaf(a[i], bb[j], acc[i][j]);
        }
        __syncthreads();
    }
    float* C = g_X1p + (size_t)blockIdx.z * MN;
    #pragma unroll
    for (int i = 0; i < 4; i++) {
        float4 v = make_float4(acc[i][0], acc[i][1], acc[i][2], acc[i][3]);
        *(float4*)&C[(size_t)(m0 + ty * 4 + i) * 512 + n0 + tx * 4] = v;
    }
}

// ---------------------------------------------------------------------------
// X1 = relu(sum_p X1p[p] + b1)
// ---------------------------------------------------------------------------
__global__ void __launch_bounds__(256) reduce_x1(const float* __restrict__ b1) {
    int i = blockIdx.x * 256 + threadIdx.x;
    float s = 0.f;
    #pragma unroll
    for (int p = 0; p < 8; p++) s += g_X1p[(size_t)p * MN + i];
    s += b1[i & 511];
    g_X1[i] = fmaxf(s, 0.f);
}

// ---------------------------------------------------------------------------
// Generic split-K GEMM: Cp[z] = Asum @ B^T  (A may be APART partials + bias)
// A is [M=512, lda] (partials strided by MN). B row-major [NB, ldb], rows >= NB -> 0.
// grid (8, 8, SK), 256 threads.
// ---------------------------------------------------------------------------
template<int APART, bool ABIAS>
__global__ void __launch_bounds__(256) gemm_sk(
    const float* __restrict__ A, const float* __restrict__ Abias, int lda,
    const float* __restrict__ Bm, int ldb, int NB,
    float* __restrict__ Cp, int kchunk) {
    __shared__ float As[16][64];
    __shared__ float Bs[16][64];
    const int t = threadIdx.x;
    const int m0 = blockIdx.y * 64, n0 = blockIdx.x * 64;
    const int lr = t >> 2, lc = (t & 3) * 4;
    const int tx = t & 15, ty = t >> 4;
    float acc[4][4] = {};
    const int kbeg = blockIdx.z * kchunk;

    for (int k0 = kbeg; k0 < kbeg + kchunk; k0 += 16) {
        int k = k0 + lc;
        float4 va = ld4(A + (size_t)(m0 + lr) * lda + k);
        #pragma unroll
        for (int p = 1; p < APART; p++) {
            float4 vp = ld4(A + (size_t)p * MN + (size_t)(m0 + lr) * lda + k);
            va.x += vp.x; va.y += vp.y; va.z += vp.z; va.w += vp.w;
        }
        if (ABIAS) {
            float4 vb = ld4(Abias + k);
            va.x += vb.x; va.y += vb.y; va.z += vb.z; va.w += vb.w;
        }
        As[lc + 0][lr] = va.x; As[lc + 1][lr] = va.y;
        As[lc + 2][lr] = va.z; As[lc + 3][lr] = va.w;
        float4 vb4 = make_float4(0.f, 0.f, 0.f, 0.f);
        if (n0 + lr < NB) vb4 = ld4(Bm + (size_t)(n0 + lr) * ldb + k);
        Bs[lc + 0][lr] = vb4.x; Bs[lc + 1][lr] = vb4.y;
        Bs[lc + 2][lr] = vb4.z; Bs[lc + 3][lr] = vb4.w;
        __syncthreads();
        #pragma unroll
        for (int kk = 0; kk < 16; kk++) {
            float a[4], bb[4];
            *(float4*)a  = *(const float4*)&As[kk][ty * 4];
            *(float4*)bb = *(const float4*)&Bs[kk][tx * 4];
            #pragma unroll
            for (int i = 0; i < 4; i++)
                #pragma unroll
                for (int j = 0; j < 4; j++)
                    acc[i][j] = fmaf(a[i], bb[j], acc[i][j]);
        }
        __syncthreads();
    }
    float* C = Cp + (size_t)blockIdx.z * MN;
    #pragma unroll
    for (int i = 0; i < 4; i++) {
        float4 v = make_float4(acc[i][0], acc[i][1], acc[i][2], acc[i][3]);
        *(float4*)&C[(size_t)(m0 + ty * 4 + i) * 512 + n0 + tx * 4] = v;
    }
}

// ---------------------------------------------------------------------------
// Threefry-2x32 (20 rounds). JAX partitionable bits = o0 ^ o1, counter (0, i).
// ---------------------------------------------------------------------------
__device__ __forceinline__ uint32_t jax_bits(uint32_t i) {
    uint32_t k0 = 0u, k1 = 42u;
    uint32_t k2 = k0 ^ k1 ^ 0x1BD11BDAu;
    uint32_t x0 = k0, x1 = i + k1;
#define TF_R(r) { x0 += x1; x1 = (x1 << (r)) | (x1 >> (32 - (r))); x1 ^= x0; }
    TF_R(13) TF_R(15) TF_R(26) TF_R(6)   x0 += k1; x1 += k2 + 1u;
    TF_R(17) TF_R(29) TF_R(16) TF_R(24)  x0 += k2; x1 += k0 + 2u;
    TF_R(13) TF_R(15) TF_R(26) TF_R(6)   x0 += k0; x1 += k1 + 3u;
    TF_R(17) TF_R(29) TF_R(16) TF_R(24)  x0 += k1; x1 += k2 + 4u;
    TF_R(13) TF_R(15) TF_R(26) TF_R(6)   x0 += k2; x1 += k0 + 5u;
#undef TF_R
    return x0 ^ x1;
}

__device__ __forceinline__ float dot8(float4 v0, float4 v1, const float* x) {
    return v0.x * x[0] + v0.y * x[1] + v0.z * x[2] + v0.w * x[3]
         + v1.x * x[4] + v1.y * x[5] + v1.z * x[6] + v1.w * x[7];
}

// ---------------------------------------------------------------------------
// Gather + masked softmax + entropy + gumbel argmax. 1 block/row, 512 threads.
// Warp w handles actions [w*64, (w+1)*64), 2 in flight.
// ---------------------------------------------------------------------------
__global__ void __launch_bounds__(512) score_softmax_sample(
    const int* __restrict__ r_space,
    const int* __restrict__ e_space,
    const float* __restrict__ mask,
    const float* __restrict__ ent_emb,
    const float* __restrict__ W2_b,
    float* __restrict__ out) {
    int b = blockIdx.x;
    int tid = threadIdx.x;
    int lane = tid & 31;
    int w = tid >> 5;           // 0..15

    __shared__ float sX2[256];
    __shared__ float sSc[1024];
    __shared__ float sMax[16];
    __shared__ float sSum[16];
    __shared__ float sV[16];
    __shared__ float sE[16];
    __shared__ int   sI[16];

    if (tid < 256) {
        float v = W2_b[256 + tid];
        #pragma unroll
        for (int p = 0; p < 4; p++) v += g_X2p[(size_t)p * MN + b * 512 + 256 + tid];
        sX2[tid] = v;
    }
    __syncthreads();

    float x[8];
    #pragma unroll
    for (int j = 0; j < 8; j++) x[j] = sX2[lane * 8 + j];

    const int base = b * A_SZ;

    // ---- scores (2 actions in flight per warp) ----
    for (int it = 0; it < 64; it += 2) {
        int a0 = w * 64 + it;
        int a1 = a0 + 1;
        int e0 = e_space[base + a0];
        int e1 = e_space[base + a1];
        const float4* p0 = (const float4*)(ent_emb + (size_t)e0 * 256 + lane * 8);
        const float4* p1 = (const float4*)(ent_emb + (size_t)e1 * 256 + lane * 8);
        float4 v00 = p0[0], v01 = p0[1];
        float4 v10 = p1[0], v11 = p1[1];
        float s0 = dot8(v00, v01, x);
        float s1 = dot8(v10, v11, x);
        #pragma unroll
        for (int o = 16; o; o >>= 1) {
            s0 += __shfl_xor_sync(0xFFFFFFFFu, s0, o);
            s1 += __shfl_xor_sync(0xFFFFFFFFu, s1, o);
        }
        if (lane == 0) {
            int r0 = r_space[base + a0];
            int r1 = r_space[base + a1];
            float rs0 = g_relSp[b * 512 + r0] + g_relSp[MN + b * 512 + r0];
            float rs1 = g_relSp[b * 512 + r1] + g_relSp[MN + b * 512 + r1];
            sSc[a0] = s0 + rs0 - (1.0f - mask[base + a0]) * 1e9f;
            sSc[a1] = s1 + rs1 - (1.0f - mask[base + a1]) * 1e9f;
        }
    }
    __syncthreads();

    // ---- max ----
    float mx = -__int_as_float(0x7F800000);
    for (int j = tid; j < 1024; j += 512) mx = fmaxf(mx, sSc[j]);
    #pragma unroll
    for (int o = 16; o; o >>= 1) mx = fmaxf(mx, __shfl_xor_sync(0xFFFFFFFFu, mx, o));
    if (lane == 0) sMax[w] = mx;
    __syncthreads();
    mx = sMax[0];
    #pragma unroll
    for (int i = 1; i < 16; i++) mx = fmaxf(mx, sMax[i]);

    // ---- exp & sum ----
    float sum = 0.f;
    for (int j = tid; j < 1024; j += 512) {
        float e = expf(sSc[j] - mx);
        sSc[j] = e;
        sum += e;
    }
    #pragma unroll
    for (int o = 16; o; o >>= 1) sum += __shfl_xor_sync(0xFFFFFFFFu, sum, o);
    if (lane == 0) sSum[w] = sum;
    __syncthreads();
    float total = 0.f;
    #pragma unroll
    for (int i = 0; i < 16; i++) total += sSum[i];

    // ---- p, entropy, gumbel argmax ----
    float ent = 0.f;
    float bestV = -__int_as_float(0x7F800000);
    int bestI = 0x7FFFFFFF;
    for (int j = tid; j < 1024; j += 512) {
        float p = sSc[j] / total;
        sSc[j] = p;
        out[1536 + base + j] = p;                 // action_dist
        float lp = logf(p + 1e-30f);
        ent += p * lp;
        uint32_t bits = jax_bits((uint32_t)(base + j));
        float f = __uint_as_float((bits >> 9) | 0x3F800000u) - 1.0f;
        float u = fmaxf(f, 1.17549435e-38f);
        float g = -logf(-logf(u));
        float v = lp + g;
        if (v > bestV || (v == bestV && j < bestI)) { bestV = v; bestI = j; }
    }
    #pragma unroll
    for (int o = 16; o; o >>= 1) {
        float ov = __shfl_xor_sync(0xFFFFFFFFu, bestV, o);
        int   oi = __shfl_xor_sync(0xFFFFFFFFu, bestI, o);
        float oe = __shfl_xor_sync(0xFFFFFFFFu, ent, o);
        ent += oe;
        if (ov > bestV || (ov == bestV && oi < bestI)) { bestV = ov; bestI = oi; }
    }
    if (lane == 0) { sV[w] = bestV; sI[w] = bestI; sE[w] = ent; }
    __syncthreads();

    if (tid == 0) {
        float bv = sV[0]; int bi = sI[0]; float te = sE[0];
        #pragma unroll
        for (int i = 1; i < 16; i++) {
            te += sE[i];
            if (sV[i] > bv || (sV[i] == bv && sI[i] < bi)) { bv = sV[i]; bi = sI[i]; }
        }
        out[b]        = sSc[bi];                          // action_prob
        out[512 + b]  = (float)r_space[base + bi];        // next_r
        out[1024 + b] = (float)e_space[base + bi];        // next_e
        out[525824 + b] = -te;                            // entropy
    }
}

// ---------------------------------------------------------------------------
extern "C" void kernel_launch(void* const* d_in, const int* in_sizes, int n_in,
                              void* d_out, int out_size) {
    const float* e_t     = (const float*)d_in[0];
    const float* Hs      = (const float*)d_in[1];
    const float* r_q     = (const float*)d_in[2];
    const int*   r_space = (const int*)d_in[3];
    const int*   e_space = (const int*)d_in[4];
    const float* mask    = (const float*)d_in[5];
    const float* W1_w    = (const float*)d_in[6];
    const float* W1_b    = (const float*)d_in[7];
    const float* W2_w    = (const float*)d_in[8];
    const float* W2_b    = (const float*)d_in[9];
    const float* rel_emb = (const float*)d_in[10];
    const float* ent_emb = (const float*)d_in[11];
    float* out = (float*)d_out;

    float *X1, *X2p, *relSp;
    cudaGetSymbolAddress((void**)&X1,    g_X1);
    cudaGetSymbolAddress((void**)&X2p,   g_X2p);
    cudaGetSymbolAddress((void**)&relSp, g_relSp);

    // X1p[sk] = concat @ W1^T  (K=1024, SK=8)
    gemm1_fused<<<dim3(8, 8, 8), 256>>>(e_t, Hs, r_q, W1_w);
    // X1 = relu(sum + b1)
    reduce_x1<<<MN / 256, 256>>>(W1_b);
    // X2p[sk] = X1 @ W2^T  (K=512, SK=4; bias folded into consumers)
    gemm_sk<1, false><<<dim3(8, 8, 4), 256>>>(X1, nullptr, 512, W2_w, 512, 512, X2p, 128);
    // relSp[sk] = (X2[:, :256] = sum X2p + b2) @ rel_emb^T  (K=256, SK=2)
    gemm_sk<4, true><<<dim3(8, 8, 2), 256>>>(X2p, W2_b, 512, rel_emb, 256, NREL, relSp, 128);
    // gather + softmax + entropy + sample
    score_softmax_sample<<<B_SZ, 512>>>(r_space, e_space, mask, ent_emb, W2_b, out);
}